// round 9
// baseline (speedup 1.0000x reference)
#include <cuda_runtime.h>
#include <cuda_bf16.h>
#include <cuda_fp16.h>
#include <math.h>
#include <stdint.h>

// ---------------- problem constants ----------------
#define BATCH 4
#define SEQ 4096
#define DMODEL 1024
#define NHEAD 16
#define DH 64
#define MTOK (BATCH*SEQ)   // 16384
#define ACT_ELEMS ((size_t)MTOK * DMODEL)
#define W_ELEMS   ((size_t)DMODEL * DMODEL)

// ---------------- scratch (__device__ globals; allocation-free rule) ------
__device__ float g_q [ACT_ELEMS];
__device__ float g_k [ACT_ELEMS];
__device__ float g_v [ACT_ELEMS];
// slice 0: Q acts bf16 (later reused as ao fp16), 1: K acts bf16, 2: V acts fp16
__device__ __nv_bfloat16 g_xh[3 * ACT_ELEMS];
__device__ __nv_bfloat16 g_xl[3 * ACT_ELEMS];
// slice 0: Wq-hi bf16, 1: Wk-hi bf16, 2: Wv fp16 (single), 3: Wo fp16 (single)
__device__ __nv_bfloat16 g_wh[4 * W_ELEMS];
__device__ __nv_bfloat16 g_wl[4 * W_ELEMS];   // lo used only for slices 0,1

// ---------------- small PTX helpers (base ISA only) ----------------
__device__ __forceinline__ uint32_t smem_u32(const void* p) {
    uint32_t a;
    asm("{ .reg .u64 t; cvta.to.shared.u64 t, %1; cvt.u32.u64 %0, t; }" : "=r"(a) : "l"(p));
    return a;
}

#define CP_ASYNC16(saddr, gptr) \
    asm volatile("cp.async.cg.shared.global [%0], [%1], 16;" :: "r"((uint32_t)(saddr)), "l"(gptr))
#define CP_COMMIT() asm volatile("cp.async.commit_group;" ::: "memory")
#define CP_WAIT(n)  asm volatile("cp.async.wait_group %0;" :: "n"(n) : "memory")

#define LDSM_X4(r, addr) \
    asm volatile("ldmatrix.sync.aligned.m8n8.x4.shared.b16 {%0,%1,%2,%3}, [%4];" \
        : "=r"((r)[0]), "=r"((r)[1]), "=r"((r)[2]), "=r"((r)[3]) : "r"(addr))

__device__ __forceinline__ void mma16816(float* d, const uint32_t* a, const uint32_t* b) {
    asm volatile(
        "mma.sync.aligned.m16n8k16.row.col.f32.bf16.bf16.f32 "
        "{%0,%1,%2,%3}, {%4,%5,%6,%7}, {%8,%9}, {%0,%1,%2,%3};"
        : "+f"(d[0]), "+f"(d[1]), "+f"(d[2]), "+f"(d[3])
        : "r"(a[0]), "r"(a[1]), "r"(a[2]), "r"(a[3]), "r"(b[0]), "r"(b[1]));
}

__device__ __forceinline__ void mma16816h(float* d, const uint32_t* a, const uint32_t* b) {
    asm volatile(
        "mma.sync.aligned.m16n8k16.row.col.f32.f16.f16.f32 "
        "{%0,%1,%2,%3}, {%4,%5,%6,%7}, {%8,%9}, {%0,%1,%2,%3};"
        : "+f"(d[0]), "+f"(d[1]), "+f"(d[2]), "+f"(d[3])
        : "r"(a[0]), "r"(a[1]), "r"(a[2]), "r"(a[3]), "r"(b[0]), "r"(b[1]));
}

// ---------------- splits ----------------
__device__ __forceinline__ void split4_bf16(float4 x, uint2& H, uint2& L) {
    __nv_bfloat162 h01 = __floats2bfloat162_rn(x.x, x.y);
    __nv_bfloat162 h23 = __floats2bfloat162_rn(x.z, x.w);
    float2 f01 = __bfloat1622float2(h01);
    float2 f23 = __bfloat1622float2(h23);
    __nv_bfloat162 l01 = __floats2bfloat162_rn(x.x - f01.x, x.y - f01.y);
    __nv_bfloat162 l23 = __floats2bfloat162_rn(x.z - f23.x, x.w - f23.y);
    H.x = *reinterpret_cast<unsigned int*>(&h01);
    H.y = *reinterpret_cast<unsigned int*>(&h23);
    L.x = *reinterpret_cast<unsigned int*>(&l01);
    L.y = *reinterpret_cast<unsigned int*>(&l23);
}

__device__ __forceinline__ void split4_f16(float4 x, uint2& H, uint2& L) {
    __half2 h01 = __floats2half2_rn(x.x, x.y);
    __half2 h23 = __floats2half2_rn(x.z, x.w);
    float2 f01 = __half22float2(h01);
    float2 f23 = __half22float2(h23);
    __half2 l01 = __floats2half2_rn(x.x - f01.x, x.y - f01.y);
    __half2 l23 = __floats2half2_rn(x.z - f23.x, x.w - f23.y);
    H.x = *reinterpret_cast<unsigned int*>(&h01);
    H.y = *reinterpret_cast<unsigned int*>(&h23);
    L.x = *reinterpret_cast<unsigned int*>(&l01);
    L.y = *reinterpret_cast<unsigned int*>(&l23);
}

// acts: y=0 query(bf16 split), y=1 key_(bf16 split), y=2 value(fp16 split)
__global__ void __launch_bounds__(256) split_acts_kernel(
    const float4* __restrict__ s0, const float4* __restrict__ s1, const float4* __restrict__ s2,
    uint2* __restrict__ hi, uint2* __restrict__ lo, int n4)
{
    int i = blockIdx.x * blockDim.x + threadIdx.x;
    if (i >= n4) return;
    int which = blockIdx.y;
    uint2 H, L;
    if (which == 0)      split4_bf16(s0[i], H, L);
    else if (which == 1) split4_bf16(s1[i], H, L);
    else                 split4_f16 (s2[i], H, L);
    hi[(size_t)which * n4 + i] = H;
    lo[(size_t)which * n4 + i] = L;
}

// weights: y=0 Wq / y=1 Wk bf16 split; y=2 Wv / y=3 Wo fp16 single (hi only)
__global__ void __launch_bounds__(256) split_w_kernel(
    const float4* __restrict__ s0, const float4* __restrict__ s1,
    const float4* __restrict__ s2, const float4* __restrict__ s3,
    uint2* __restrict__ hi, uint2* __restrict__ lo, int n4)
{
    int i = blockIdx.x * blockDim.x + threadIdx.x;
    if (i >= n4) return;
    int which = blockIdx.y;
    if (which < 2) {
        uint2 H, L;
        split4_bf16(which == 0 ? s0[i] : s1[i], H, L);
        hi[(size_t)which * n4 + i] = H;
        lo[(size_t)which * n4 + i] = L;
    } else {
        float4 x = (which == 2) ? s2[i] : s3[i];
        __half2 h01 = __floats2half2_rn(x.x, x.y);
        __half2 h23 = __floats2half2_rn(x.z, x.w);
        uint2 H;
        H.x = *reinterpret_cast<unsigned int*>(&h01);
        H.y = *reinterpret_cast<unsigned int*>(&h23);
        hi[(size_t)which * n4 + i] = H;
    }
}

// ================= bf16x3 GEMM (R5 config: GBK64, 1 CTA/SM, 239.6us) ======
#define GBM 128
#define GBN 128
#define GBK 64
#define KDIM DMODEL
#define NCHUNK (KDIM/GBK)      // 16
#define STAGE_BYTES 65536      // Ah 16K | Al 16K | Bh 16K | Bl 16K
#define A_HI 0
#define A_LO 16384
#define B_HI 32768
#define B_LO 49152
#define NSTAGE 3
#define GSMEM_TOTAL (NSTAGE*STAGE_BYTES)   // 196608

__global__ void __launch_bounds__(256, 1) gemm_bf16x3(
    const __nv_bfloat16* __restrict__ Ah, const __nv_bfloat16* __restrict__ Al,
    const __nv_bfloat16* __restrict__ Wh, const __nv_bfloat16* __restrict__ Wl,
    const float* __restrict__ bias, float* __restrict__ C)
{
    extern __shared__ char smem[];
    const uint32_t sb = smem_u32(smem);
    const int tid = threadIdx.x;
    const int m0 = blockIdx.y * GBM;
    const int n0 = blockIdx.x * GBN;

    const int l  = tid & 31;
    const int w  = tid >> 5;
    const int wm = (w & 3) * 32;
    const int wn = (w >> 2) * 64;

    const int rowA  = (l & 7) + ((l >> 3) & 1) * 8;
    const int kselA = (l >> 4) & 1;
    const int rowB  = (l & 7) + ((l >> 4) & 1) * 8;
    const int kselB = (l >> 3) & 1;

    float acc[2][8][4];
#pragma unroll
    for (int a = 0; a < 2; a++)
#pragma unroll
        for (int b = 0; b < 8; b++)
#pragma unroll
            for (int c = 0; c < 4; c++) acc[a][b][c] = 0.0f;

    auto load_chunk = [&](int st, int c) {
        uint32_t base = sb + st * STAGE_BYTES;
        int k0 = c * GBK;
#pragma unroll
        for (int it = 0; it < 4; it++) {
            int idx = tid + it * 256;
            int r  = idx >> 3;
            int ch = idx & 7;
            uint32_t sw = (uint32_t)(r * 128 + ((ch ^ (r & 7)) * 16));
            size_t gA = (size_t)(m0 + r) * KDIM + k0 + ch * 8;
            size_t gB = (size_t)(n0 + r) * KDIM + k0 + ch * 8;
            CP_ASYNC16(base + A_HI + sw, Ah + gA);
            CP_ASYNC16(base + A_LO + sw, Al + gA);
            CP_ASYNC16(base + B_HI + sw, Wh + gB);
            CP_ASYNC16(base + B_LO + sw, Wl + gB);
        }
    };

    uint32_t a_h[2][2][4], a_l[2][2][4], b_h[2][4][4], b_l[2][4][4];

    auto load_step = [&](uint32_t base, int s, int buf) {
#pragma unroll
        for (int mt = 0; mt < 2; mt++) {
            int row = wm + mt * 16 + rowA;
            int ch  = (s * 2 + kselA) ^ (row & 7);
            uint32_t off = (uint32_t)(row * 128 + ch * 16);
            LDSM_X4(a_h[buf][mt], base + A_HI + off);
            LDSM_X4(a_l[buf][mt], base + A_LO + off);
        }
#pragma unroll
        for (int ng = 0; ng < 4; ng++) {
            int row = wn + ng * 16 + rowB;
            int ch  = (s * 2 + kselB) ^ (row & 7);
            uint32_t off = (uint32_t)(row * 128 + ch * 16);
            LDSM_X4(b_h[buf][ng], base + B_HI + off);
            LDSM_X4(b_l[buf][ng], base + B_LO + off);
        }
    };

    auto mma_step = [&](int buf) {
#pragma unroll
        for (int p = 0; p < 3; p++) {
#pragma unroll
            for (int mt = 0; mt < 2; mt++) {
#pragma unroll
                for (int ng = 0; ng < 4; ng++) {
                    const uint32_t* A = (p == 2) ? a_l[buf][mt] : a_h[buf][mt];
                    const uint32_t* B = (p == 1) ? b_l[buf][ng] : b_h[buf][ng];
                    mma16816(acc[mt][ng * 2 + 0], A, &B[0]);
                    mma16816(acc[mt][ng * 2 + 1], A, &B[2]);
                }
            }
        }
    };

    load_chunk(0, 0); CP_COMMIT();
    load_chunk(1, 1); CP_COMMIT();

    for (int c = 0; c < NCHUNK; c++) {
        int st = c % NSTAGE;
        uint32_t base = sb + st * STAGE_BYTES;
        if (c + 2 < NCHUNK) { CP_WAIT(1); } else { CP_WAIT(0); }
        __syncthreads();
        if (c + 2 < NCHUNK) {
            load_chunk((c + 2) % NSTAGE, c + 2); CP_COMMIT();
        }
        load_step(base, 0, 0);
#pragma unroll
        for (int s = 0; s < 4; s++) {
            if (s < 3) load_step(base, s + 1, (s + 1) & 1);
            mma_step(s & 1);
        }
    }

    const int g  = l >> 2;
    const int tg = l & 3;
#pragma unroll
    for (int mt = 0; mt < 2; mt++) {
#pragma unroll
        for (int nt = 0; nt < 8; nt++) {
            int n = n0 + wn + nt * 8 + tg * 2;
            float bx = bias[n], by = bias[n + 1];
            int mA = m0 + wm + mt * 16 + g;
            float2 lo = make_float2(acc[mt][nt][0] + bx, acc[mt][nt][1] + by);
            float2 hi = make_float2(acc[mt][nt][2] + bx, acc[mt][nt][3] + by);
            *(float2*)(C + (size_t)mA * DMODEL + n)       = lo;
            *(float2*)(C + (size_t)(mA + 8) * DMODEL + n) = hi;
        }
    }
}

// ================= fp16x2 GEMM: C = (Ah+Al) @ Wh^T + bias =================
// A double-split fp16, W single fp16; 2 products (Ah*Wh + Al*Wh).
#define HSTAGE_BYTES 49152     // Ah 16K | Al 16K | Bh 16K
#define H_A_HI 0
#define H_A_LO 16384
#define H_B_HI 32768
#define HSMEM_TOTAL (NSTAGE*HSTAGE_BYTES)  // 147456

__global__ void __launch_bounds__(256, 1) gemm_fp16x2(
    const __half* __restrict__ Ah, const __half* __restrict__ Al,
    const __half* __restrict__ Wh,
    const float* __restrict__ bias, float* __restrict__ C)
{
    extern __shared__ char smem[];
    const uint32_t sb = smem_u32(smem);
    const int tid = threadIdx.x;
    const int m0 = blockIdx.y * GBM;
    const int n0 = blockIdx.x * GBN;

    const int l  = tid & 31;
    const int w  = tid >> 5;
    const int wm = (w & 3) * 32;
    const int wn = (w >> 2) * 64;

    const int rowA  = (l & 7) + ((l >> 3) & 1) * 8;
    const int kselA = (l >> 4) & 1;
    const int rowB  = (l & 7) + ((l >> 4) & 1) * 8;
    const int kselB = (l >> 3) & 1;

    float acc[2][8][4];
#pragma unroll
    for (int a = 0; a < 2; a++)
#pragma unroll
        for (int b = 0; b < 8; b++)
#pragma unroll
            for (int c = 0; c < 4; c++) acc[a][b][c] = 0.0f;

    auto load_chunk = [&](int st, int c) {
        uint32_t base = sb + st * HSTAGE_BYTES;
        int k0 = c * GBK;
#pragma unroll
        for (int it = 0; it < 4; it++) {
            int idx = tid + it * 256;
            int r  = idx >> 3;
            int ch = idx & 7;
            uint32_t sw = (uint32_t)(r * 128 + ((ch ^ (r & 7)) * 16));
            size_t gA = (size_t)(m0 + r) * KDIM + k0 + ch * 8;
            size_t gB = (size_t)(n0 + r) * KDIM + k0 + ch * 8;
            CP_ASYNC16(base + H_A_HI + sw, Ah + gA);
            CP_ASYNC16(base + H_A_LO + sw, Al + gA);
            CP_ASYNC16(base + H_B_HI + sw, Wh + gB);
        }
    };

    load_chunk(0, 0); CP_COMMIT();
    load_chunk(1, 1); CP_COMMIT();

    uint32_t a_h[2][4], a_l[2][4], b[4][4];

    for (int c = 0; c < NCHUNK; c++) {
        int st = c % NSTAGE;
        uint32_t base = sb + st * HSTAGE_BYTES;
        if (c + 2 < NCHUNK) { CP_WAIT(1); } else { CP_WAIT(0); }
        __syncthreads();
        if (c + 2 < NCHUNK) {
            load_chunk((c + 2) % NSTAGE, c + 2); CP_COMMIT();
        }
#pragma unroll
        for (int s = 0; s < 4; s++) {
#pragma unroll
            for (int mt = 0; mt < 2; mt++) {
                int row = wm + mt * 16 + rowA;
                int ch  = (s * 2 + kselA) ^ (row & 7);
                uint32_t off = (uint32_t)(row * 128 + ch * 16);
                LDSM_X4(a_h[mt], base + H_A_HI + off);
                LDSM_X4(a_l[mt], base + H_A_LO + off);
            }
#pragma unroll
            for (int ng = 0; ng < 4; ng++) {
                int row = wn + ng * 16 + rowB;
                int ch  = (s * 2 + kselB) ^ (row & 7);
                LDSM_X4(b[ng], base + H_B_HI + (uint32_t)(row * 128 + ch * 16));
            }
#pragma unroll
            for (int mt = 0; mt < 2; mt++)
#pragma unroll
                for (int ng = 0; ng < 4; ng++) {
                    mma16816h(acc[mt][ng * 2 + 0], a_h[mt], &b[ng][0]);
                    mma16816h(acc[mt][ng * 2 + 1], a_h[mt], &b[ng][2]);
                }
#pragma unroll
            for (int mt = 0; mt < 2; mt++)
#pragma unroll
                for (int ng = 0; ng < 4; ng++) {
                    mma16816h(acc[mt][ng * 2 + 0], a_l[mt], &b[ng][0]);
                    mma16816h(acc[mt][ng * 2 + 1], a_l[mt], &b[ng][2]);
                }
        }
    }

    const int g  = l >> 2;
    const int tg = l & 3;
#pragma unroll
    for (int mt = 0; mt < 2; mt++) {
#pragma unroll
        for (int nt = 0; nt < 8; nt++) {
            int n = n0 + wn + nt * 8 + tg * 2;
            float bx = bias[n], by = bias[n + 1];
            int mA = m0 + wm + mt * 16 + g;
            float2 lo = make_float2(acc[mt][nt][0] + bx, acc[mt][nt][1] + by);
            float2 hi = make_float2(acc[mt][nt][2] + bx, acc[mt][nt][3] + by);
            *(float2*)(C + (size_t)mA * DMODEL + n)       = lo;
            *(float2*)(C + (size_t)(mA + 8) * DMODEL + n) = hi;
        }
    }
}

// ---------------- per-token attention, online softmax ----------
// Writes output as fp16 hi/lo splits (A operand of the fp16x2 O projection).
__global__ __launch_bounds__(128) void attn_per_token(
    const float* __restrict__ q, const float* __restrict__ k,
    const float* __restrict__ v,
    __half* __restrict__ aoh, __half* __restrict__ aol)
{
    const int half_ = threadIdx.x >> 6;
    const int t = blockIdx.x * 2 + half_;
    const int i = threadIdx.x & 63;

    __shared__ float sk[2][DMODEL];
    __shared__ float sv[2][DMODEL];

    const float* kt = k + (size_t)t * DMODEL;
    const float* vt = v + (size_t)t * DMODEL;
#pragma unroll
    for (int f = i; f < 256; f += 64) {
        ((float4*)sk[half_])[f] = ((const float4*)kt)[f];
        ((float4*)sv[half_])[f] = ((const float4*)vt)[f];
    }
    __syncthreads();

    float4 q4[4];
    const float4* qt = (const float4*)(q + (size_t)t * DMODEL + i * NHEAD);
#pragma unroll
    for (int hg = 0; hg < 4; hg++) {
        float4 tq = qt[hg];
        q4[hg] = make_float4(tq.x * 32.0f, tq.y * 32.0f, tq.z * 32.0f, tq.w * 32.0f);
    }

    const float4* k4 = (const float4*)sk[half_];
    const float4* v4 = (const float4*)sv[half_];

    float m = -1e30f, ssum = 0.0f;
    float4 o4[4];
#pragma unroll
    for (int hg = 0; hg < 4; hg++) o4[hg] = make_float4(0.f, 0.f, 0.f, 0.f);

#pragma unroll
    for (int jc = 0; jc < 4; jc++) {
        float sc[16];
        float cm = -1e30f;
#pragma unroll
        for (int jj = 0; jj < 16; jj++) {
            int j = jc * 16 + jj;
            float4 a = make_float4(0.f, 0.f, 0.f, 0.f);
#pragma unroll
            for (int hg = 0; hg < 4; hg++) {
                float4 kk = k4[j * 4 + hg];
                a.x = fmaf(q4[hg].x, kk.x, a.x);
                a.y = fmaf(q4[hg].y, kk.y, a.y);
                a.z = fmaf(q4[hg].z, kk.z, a.z);
                a.w = fmaf(q4[hg].w, kk.w, a.w);
            }
            sc[jj] = (a.x + a.y) + (a.z + a.w);
            cm = fmaxf(cm, sc[jj]);
        }
        float nm = fmaxf(m, cm);
        float scale = __expf(m - nm);
        ssum *= scale;
#pragma unroll
        for (int hg = 0; hg < 4; hg++) {
            o4[hg].x *= scale; o4[hg].y *= scale;
            o4[hg].z *= scale; o4[hg].w *= scale;
        }
#pragma unroll
        for (int jj = 0; jj < 16; jj++) {
            int j = jc * 16 + jj;
            float p = __expf(sc[jj] - nm);
            ssum += p;
#pragma unroll
            for (int hg = 0; hg < 4; hg++) {
                float4 vv = v4[j * 4 + hg];
                o4[hg].x = fmaf(p, vv.x, o4[hg].x);
                o4[hg].y = fmaf(p, vv.y, o4[hg].y);
                o4[hg].z = fmaf(p, vv.z, o4[hg].z);
                o4[hg].w = fmaf(p, vv.w, o4[hg].w);
            }
        }
        m = nm;
    }

    const float inv = 1.0f / ssum;
    float o[NHEAD];
#pragma unroll
    for (int hg = 0; hg < 4; hg++) {
        o[hg * 4 + 0] = o4[hg].x * inv;
        o[hg * 4 + 1] = o4[hg].y * inv;
        o[hg * 4 + 2] = o4[hg].z * inv;
        o[hg * 4 + 3] = o4[hg].w * inv;
    }

    uint32_t hi8[8], lo8[8];
#pragma unroll
    for (int p = 0; p < 8; p++) {
        float x = o[2 * p], y = o[2 * p + 1];
        __half2 h2 = __floats2half2_rn(x, y);
        float2 hf = __half22float2(h2);
        __half2 l2 = __floats2half2_rn(x - hf.x, y - hf.y);
        hi8[p] = *reinterpret_cast<uint32_t*>(&h2);
        lo8[p] = *reinterpret_cast<uint32_t*>(&l2);
    }
    size_t obase = (size_t)t * DMODEL + i * NHEAD;
    *(uint4*)(aoh + obase)     = make_uint4(hi8[0], hi8[1], hi8[2], hi8[3]);
    *(uint4*)(aoh + obase + 8) = make_uint4(hi8[4], hi8[5], hi8[6], hi8[7]);
    *(uint4*)(aol + obase)     = make_uint4(lo8[0], lo8[1], lo8[2], lo8[3]);
    *(uint4*)(aol + obase + 8) = make_uint4(lo8[4], lo8[5], lo8[6], lo8[7]);
}

// ---------------- launch ----------------
extern "C" void kernel_launch(void* const* d_in, const int* in_sizes, int n_in,
                              void* d_out, int out_size)
{
    const float* query = (const float*)d_in[0];
    const float* key_  = (const float*)d_in[1];
    const float* value = (const float*)d_in[2];
    const float* Wq    = (const float*)d_in[3];
    const float* bq    = (const float*)d_in[4];
    const float* Wk    = (const float*)d_in[5];
    const float* bk    = (const float*)d_in[6];
    const float* Wv    = (const float*)d_in[7];
    const float* bv    = (const float*)d_in[8];
    const float* Wo    = (const float*)d_in[9];
    const float* bo    = (const float*)d_in[10];
    float* out = (float*)d_out;

    float *q, *k, *v;
    __nv_bfloat16 *xh, *xl, *wh, *wl;
    cudaGetSymbolAddress((void**)&q,  g_q);
    cudaGetSymbolAddress((void**)&k,  g_k);
    cudaGetSymbolAddress((void**)&v,  g_v);
    cudaGetSymbolAddress((void**)&xh, g_xh);
    cudaGetSymbolAddress((void**)&xl, g_xl);
    cudaGetSymbolAddress((void**)&wh, g_wh);
    cudaGetSymbolAddress((void**)&wl, g_wl);

    cudaFuncSetAttribute(gemm_bf16x3, cudaFuncAttributeMaxDynamicSharedMemorySize, GSMEM_TOTAL);
    cudaFuncSetAttribute(gemm_fp16x2, cudaFuncAttributeMaxDynamicSharedMemorySize, HSMEM_TOTAL);

    const int nAct4 = (int)(ACT_ELEMS / 4);
    const int nW4   = (int)(W_ELEMS / 4);
    dim3 sgA((nAct4 + 255) / 256, 3);
    dim3 sgW((nW4 + 255) / 256, 4);
    dim3 ggrid(DMODEL / GBN, MTOK / GBM);   // (8, 128)

    split_acts_kernel<<<sgA, 256>>>((const float4*)query, (const float4*)key_,
                                    (const float4*)value, (uint2*)xh, (uint2*)xl, nAct4);
    split_w_kernel<<<sgW, 256>>>((const float4*)Wq, (const float4*)Wk,
                                 (const float4*)Wv, (const float4*)Wo,
                                 (uint2*)wh, (uint2*)wl, nW4);

    // Q, K projections: bf16x3 (score-critical precision)
    gemm_bf16x3<<<ggrid, 256, GSMEM_TOTAL>>>(xh,             xl,             wh,           wl,           bq, q);
    gemm_bf16x3<<<ggrid, 256, GSMEM_TOTAL>>>(xh + ACT_ELEMS, xl + ACT_ELEMS, wh + W_ELEMS, wl + W_ELEMS, bk, k);
    // V projection: fp16x2
    gemm_fp16x2<<<ggrid, 256, HSMEM_TOTAL>>>((const __half*)(xh + 2 * ACT_ELEMS),
                                             (const __half*)(xl + 2 * ACT_ELEMS),
                                             (const __half*)(wh + 2 * W_ELEMS), bv, v);

    // attention: writes ao fp16 hi/lo into slice 0 of xh/xl
    attn_per_token<<<MTOK / 2, 128>>>(q, k, v, (__half*)xh, (__half*)xl);

    // O projection: fp16x2
    gemm_fp16x2<<<ggrid, 256, HSMEM_TOTAL>>>((const __half*)xh, (const __half*)xl,
                                             (const __half*)(wh + 3 * W_ELEMS), bo, out);
}

// round 10
// speedup vs baseline: 1.1288x; 1.1288x over previous
#include <cuda_runtime.h>
#include <cuda_bf16.h>
#include <cuda_fp16.h>
#include <math.h>
#include <stdint.h>

// ---------------- problem constants ----------------
#define BATCH 4
#define SEQ 4096
#define DMODEL 1024
#define NHEAD 16
#define DH 64
#define MTOK (BATCH*SEQ)   // 16384
#define ACT_ELEMS ((size_t)MTOK * DMODEL)
#define W_ELEMS   ((size_t)DMODEL * DMODEL)

// ---------------- scratch (__device__ globals; allocation-free rule) ------
__device__ float g_q [ACT_ELEMS];
__device__ float g_k [ACT_ELEMS];
__device__ float g_v [ACT_ELEMS];
// slice 0: Q acts bf16-hi (later reused as ao fp16), 1: K acts bf16-hi, 2: V acts fp16
__device__ __nv_bfloat16 g_xh[3 * ACT_ELEMS];
__device__ __nv_bfloat16 g_xl[3 * ACT_ELEMS];   // lo splits for slices 0,1 only
// slice 0: Wq-hi bf16, 1: Wk-hi bf16, 2: Wv fp16 (single), 3: Wo fp16 (single)
__device__ __nv_bfloat16 g_wh[4 * W_ELEMS];
__device__ __nv_bfloat16 g_wl[4 * W_ELEMS];     // lo used only for slices 0,1

// ---------------- small PTX helpers (base ISA only) ----------------
__device__ __forceinline__ uint32_t smem_u32(const void* p) {
    uint32_t a;
    asm("{ .reg .u64 t; cvta.to.shared.u64 t, %1; cvt.u32.u64 %0, t; }" : "=r"(a) : "l"(p));
    return a;
}

#define CP_ASYNC16(saddr, gptr) \
    asm volatile("cp.async.cg.shared.global [%0], [%1], 16;" :: "r"((uint32_t)(saddr)), "l"(gptr))
#define CP_COMMIT() asm volatile("cp.async.commit_group;" ::: "memory")
#define CP_WAIT(n)  asm volatile("cp.async.wait_group %0;" :: "n"(n) : "memory")

#define LDSM_X4(r, addr) \
    asm volatile("ldmatrix.sync.aligned.m8n8.x4.shared.b16 {%0,%1,%2,%3}, [%4];" \
        : "=r"((r)[0]), "=r"((r)[1]), "=r"((r)[2]), "=r"((r)[3]) : "r"(addr))

__device__ __forceinline__ void mma16816(float* d, const uint32_t* a, const uint32_t* b) {
    asm volatile(
        "mma.sync.aligned.m16n8k16.row.col.f32.bf16.bf16.f32 "
        "{%0,%1,%2,%3}, {%4,%5,%6,%7}, {%8,%9}, {%0,%1,%2,%3};"
        : "+f"(d[0]), "+f"(d[1]), "+f"(d[2]), "+f"(d[3])
        : "r"(a[0]), "r"(a[1]), "r"(a[2]), "r"(a[3]), "r"(b[0]), "r"(b[1]));
}

__device__ __forceinline__ void mma16816h(float* d, const uint32_t* a, const uint32_t* b) {
    asm volatile(
        "mma.sync.aligned.m16n8k16.row.col.f32.f16.f16.f32 "
        "{%0,%1,%2,%3}, {%4,%5,%6,%7}, {%8,%9}, {%0,%1,%2,%3};"
        : "+f"(d[0]), "+f"(d[1]), "+f"(d[2]), "+f"(d[3])
        : "r"(a[0]), "r"(a[1]), "r"(a[2]), "r"(a[3]), "r"(b[0]), "r"(b[1]));
}

// ---------------- splits ----------------
__device__ __forceinline__ void split4_bf16(float4 x, uint2& H, uint2& L) {
    __nv_bfloat162 h01 = __floats2bfloat162_rn(x.x, x.y);
    __nv_bfloat162 h23 = __floats2bfloat162_rn(x.z, x.w);
    float2 f01 = __bfloat1622float2(h01);
    float2 f23 = __bfloat1622float2(h23);
    __nv_bfloat162 l01 = __floats2bfloat162_rn(x.x - f01.x, x.y - f01.y);
    __nv_bfloat162 l23 = __floats2bfloat162_rn(x.z - f23.x, x.w - f23.y);
    H.x = *reinterpret_cast<unsigned int*>(&h01);
    H.y = *reinterpret_cast<unsigned int*>(&h23);
    L.x = *reinterpret_cast<unsigned int*>(&l01);
    L.y = *reinterpret_cast<unsigned int*>(&l23);
}

__device__ __forceinline__ uint2 pack4_f16(float4 x) {
    __half2 h01 = __floats2half2_rn(x.x, x.y);
    __half2 h23 = __floats2half2_rn(x.z, x.w);
    uint2 H;
    H.x = *reinterpret_cast<unsigned int*>(&h01);
    H.y = *reinterpret_cast<unsigned int*>(&h23);
    return H;
}

// acts: y=0 query (bf16 split), y=1 key_ (bf16 split), y=2 value (fp16 single)
__global__ void __launch_bounds__(256) split_acts_kernel(
    const float4* __restrict__ s0, const float4* __restrict__ s1, const float4* __restrict__ s2,
    uint2* __restrict__ hi, uint2* __restrict__ lo, int n4)
{
    int i = blockIdx.x * blockDim.x + threadIdx.x;
    if (i >= n4) return;
    int which = blockIdx.y;
    if (which < 2) {
        uint2 H, L;
        split4_bf16(which == 0 ? s0[i] : s1[i], H, L);
        hi[(size_t)which * n4 + i] = H;
        lo[(size_t)which * n4 + i] = L;
    } else {
        hi[(size_t)2 * n4 + i] = pack4_f16(s2[i]);
    }
}

// weights: y=0 Wq / y=1 Wk bf16 split; y=2 Wv / y=3 Wo fp16 single (hi only)
__global__ void __launch_bounds__(256) split_w_kernel(
    const float4* __restrict__ s0, const float4* __restrict__ s1,
    const float4* __restrict__ s2, const float4* __restrict__ s3,
    uint2* __restrict__ hi, uint2* __restrict__ lo, int n4)
{
    int i = blockIdx.x * blockDim.x + threadIdx.x;
    if (i >= n4) return;
    int which = blockIdx.y;
    if (which < 2) {
        uint2 H, L;
        split4_bf16(which == 0 ? s0[i] : s1[i], H, L);
        hi[(size_t)which * n4 + i] = H;
        lo[(size_t)which * n4 + i] = L;
    } else {
        hi[(size_t)which * n4 + i] = pack4_f16(which == 2 ? s2[i] : s3[i]);
    }
}

// ================= bf16x3 GEMM (GBK64, 1 CTA/SM) ==========================
#define GBM 128
#define GBN 128
#define GBK 64
#define KDIM DMODEL
#define NCHUNK (KDIM/GBK)      // 16
#define STAGE_BYTES 65536      // Ah 16K | Al 16K | Bh 16K | Bl 16K
#define A_HI 0
#define A_LO 16384
#define B_HI 32768
#define B_LO 49152
#define NSTAGE 3
#define GSMEM_TOTAL (NSTAGE*STAGE_BYTES)   // 196608

__global__ void __launch_bounds__(256, 1) gemm_bf16x3(
    const __nv_bfloat16* __restrict__ Ah, const __nv_bfloat16* __restrict__ Al,
    const __nv_bfloat16* __restrict__ Wh, const __nv_bfloat16* __restrict__ Wl,
    const float* __restrict__ bias, float* __restrict__ C)
{
    extern __shared__ char smem[];
    const uint32_t sb = smem_u32(smem);
    const int tid = threadIdx.x;
    const int m0 = blockIdx.y * GBM;
    const int n0 = blockIdx.x * GBN;

    const int l  = tid & 31;
    const int w  = tid >> 5;
    const int wm = (w & 3) * 32;
    const int wn = (w >> 2) * 64;

    const int rowA  = (l & 7) + ((l >> 3) & 1) * 8;
    const int kselA = (l >> 4) & 1;
    const int rowB  = (l & 7) + ((l >> 4) & 1) * 8;
    const int kselB = (l >> 3) & 1;

    float acc[2][8][4];
#pragma unroll
    for (int a = 0; a < 2; a++)
#pragma unroll
        for (int b = 0; b < 8; b++)
#pragma unroll
            for (int c = 0; c < 4; c++) acc[a][b][c] = 0.0f;

    auto load_chunk = [&](int st, int c) {
        uint32_t base = sb + st * STAGE_BYTES;
        int k0 = c * GBK;
#pragma unroll
        for (int it = 0; it < 4; it++) {
            int idx = tid + it * 256;
            int r  = idx >> 3;
            int ch = idx & 7;
            uint32_t sw = (uint32_t)(r * 128 + ((ch ^ (r & 7)) * 16));
            size_t gA = (size_t)(m0 + r) * KDIM + k0 + ch * 8;
            size_t gB = (size_t)(n0 + r) * KDIM + k0 + ch * 8;
            CP_ASYNC16(base + A_HI + sw, Ah + gA);
            CP_ASYNC16(base + A_LO + sw, Al + gA);
            CP_ASYNC16(base + B_HI + sw, Wh + gB);
            CP_ASYNC16(base + B_LO + sw, Wl + gB);
        }
    };

    uint32_t a_h[2][2][4], a_l[2][2][4], b_h[2][4][4], b_l[2][4][4];

    auto load_step = [&](uint32_t base, int s, int buf) {
#pragma unroll
        for (int mt = 0; mt < 2; mt++) {
            int row = wm + mt * 16 + rowA;
            int ch  = (s * 2 + kselA) ^ (row & 7);
            uint32_t off = (uint32_t)(row * 128 + ch * 16);
            LDSM_X4(a_h[buf][mt], base + A_HI + off);
            LDSM_X4(a_l[buf][mt], base + A_LO + off);
        }
#pragma unroll
        for (int ng = 0; ng < 4; ng++) {
            int row = wn + ng * 16 + rowB;
            int ch  = (s * 2 + kselB) ^ (row & 7);
            uint32_t off = (uint32_t)(row * 128 + ch * 16);
            LDSM_X4(b_h[buf][ng], base + B_HI + off);
            LDSM_X4(b_l[buf][ng], base + B_LO + off);
        }
    };

    auto mma_step = [&](int buf) {
#pragma unroll
        for (int p = 0; p < 3; p++) {
#pragma unroll
            for (int mt = 0; mt < 2; mt++) {
#pragma unroll
                for (int ng = 0; ng < 4; ng++) {
                    const uint32_t* A = (p == 2) ? a_l[buf][mt] : a_h[buf][mt];
                    const uint32_t* B = (p == 1) ? b_l[buf][ng] : b_h[buf][ng];
                    mma16816(acc[mt][ng * 2 + 0], A, &B[0]);
                    mma16816(acc[mt][ng * 2 + 1], A, &B[2]);
                }
            }
        }
    };

    load_chunk(0, 0); CP_COMMIT();
    load_chunk(1, 1); CP_COMMIT();

    for (int c = 0; c < NCHUNK; c++) {
        int st = c % NSTAGE;
        uint32_t base = sb + st * STAGE_BYTES;
        if (c + 2 < NCHUNK) { CP_WAIT(1); } else { CP_WAIT(0); }
        __syncthreads();
        if (c + 2 < NCHUNK) {
            load_chunk((c + 2) % NSTAGE, c + 2); CP_COMMIT();
        }
        load_step(base, 0, 0);
#pragma unroll
        for (int s = 0; s < 4; s++) {
            if (s < 3) load_step(base, s + 1, (s + 1) & 1);
            mma_step(s & 1);
        }
    }

    const int g  = l >> 2;
    const int tg = l & 3;
#pragma unroll
    for (int mt = 0; mt < 2; mt++) {
#pragma unroll
        for (int nt = 0; nt < 8; nt++) {
            int n = n0 + wn + nt * 8 + tg * 2;
            float bx = bias[n], by = bias[n + 1];
            int mA = m0 + wm + mt * 16 + g;
            float2 lo = make_float2(acc[mt][nt][0] + bx, acc[mt][nt][1] + by);
            float2 hi = make_float2(acc[mt][nt][2] + bx, acc[mt][nt][3] + by);
            *(float2*)(C + (size_t)mA * DMODEL + n)       = lo;
            *(float2*)(C + (size_t)(mA + 8) * DMODEL + n) = hi;
        }
    }
}

// ================= fp16x1 GEMM: C = A @ W^T + bias (single product) =======
#define H1STAGE_BYTES 32768    // A 16K | B 16K
#define H1_A 0
#define H1_B 16384
#define H1SMEM_TOTAL (NSTAGE*H1STAGE_BYTES)  // 98304

__global__ void __launch_bounds__(256, 1) gemm_fp16x1(
    const __half* __restrict__ A, const __half* __restrict__ W,
    const float* __restrict__ bias, float* __restrict__ C)
{
    extern __shared__ char smem[];
    const uint32_t sb = smem_u32(smem);
    const int tid = threadIdx.x;
    const int m0 = blockIdx.y * GBM;
    const int n0 = blockIdx.x * GBN;

    const int l  = tid & 31;
    const int w  = tid >> 5;
    const int wm = (w & 3) * 32;
    const int wn = (w >> 2) * 64;

    const int rowA  = (l & 7) + ((l >> 3) & 1) * 8;
    const int kselA = (l >> 4) & 1;
    const int rowB  = (l & 7) + ((l >> 4) & 1) * 8;
    const int kselB = (l >> 3) & 1;

    float acc[2][8][4];
#pragma unroll
    for (int a = 0; a < 2; a++)
#pragma unroll
        for (int b = 0; b < 8; b++)
#pragma unroll
            for (int c = 0; c < 4; c++) acc[a][b][c] = 0.0f;

    auto load_chunk = [&](int st, int c) {
        uint32_t base = sb + st * H1STAGE_BYTES;
        int k0 = c * GBK;
#pragma unroll
        for (int it = 0; it < 4; it++) {
            int idx = tid + it * 256;
            int r  = idx >> 3;
            int ch = idx & 7;
            uint32_t sw = (uint32_t)(r * 128 + ((ch ^ (r & 7)) * 16));
            size_t gA = (size_t)(m0 + r) * KDIM + k0 + ch * 8;
            size_t gB = (size_t)(n0 + r) * KDIM + k0 + ch * 8;
            CP_ASYNC16(base + H1_A + sw, A + gA);
            CP_ASYNC16(base + H1_B + sw, W + gB);
        }
    };

    load_chunk(0, 0); CP_COMMIT();
    load_chunk(1, 1); CP_COMMIT();

    uint32_t ra[2][4], rb[4][4];

    for (int c = 0; c < NCHUNK; c++) {
        int st = c % NSTAGE;
        uint32_t base = sb + st * H1STAGE_BYTES;
        if (c + 2 < NCHUNK) { CP_WAIT(1); } else { CP_WAIT(0); }
        __syncthreads();
        if (c + 2 < NCHUNK) {
            load_chunk((c + 2) % NSTAGE, c + 2); CP_COMMIT();
        }
#pragma unroll
        for (int s = 0; s < 4; s++) {
#pragma unroll
            for (int mt = 0; mt < 2; mt++) {
                int row = wm + mt * 16 + rowA;
                int ch  = (s * 2 + kselA) ^ (row & 7);
                LDSM_X4(ra[mt], base + H1_A + (uint32_t)(row * 128 + ch * 16));
            }
#pragma unroll
            for (int ng = 0; ng < 4; ng++) {
                int row = wn + ng * 16 + rowB;
                int ch  = (s * 2 + kselB) ^ (row & 7);
                LDSM_X4(rb[ng], base + H1_B + (uint32_t)(row * 128 + ch * 16));
            }
#pragma unroll
            for (int mt = 0; mt < 2; mt++)
#pragma unroll
                for (int ng = 0; ng < 4; ng++) {
                    mma16816h(acc[mt][ng * 2 + 0], ra[mt], &rb[ng][0]);
                    mma16816h(acc[mt][ng * 2 + 1], ra[mt], &rb[ng][2]);
                }
        }
    }

    const int g  = l >> 2;
    const int tg = l & 3;
#pragma unroll
    for (int mt = 0; mt < 2; mt++) {
#pragma unroll
        for (int nt = 0; nt < 8; nt++) {
            int n = n0 + wn + nt * 8 + tg * 2;
            float bx = bias[n], by = bias[n + 1];
            int mA = m0 + wm + mt * 16 + g;
            float2 lo = make_float2(acc[mt][nt][0] + bx, acc[mt][nt][1] + by);
            float2 hi = make_float2(acc[mt][nt][2] + bx, acc[mt][nt][3] + by);
            *(float2*)(C + (size_t)mA * DMODEL + n)       = lo;
            *(float2*)(C + (size_t)(mA + 8) * DMODEL + n) = hi;
        }
    }
}

// ---------------- per-token attention, online softmax ----------
// Writes output as single fp16 (A operand of the fp16x1 O projection).
__global__ __launch_bounds__(128) void attn_per_token(
    const float* __restrict__ q, const float* __restrict__ k,
    const float* __restrict__ v, __half* __restrict__ ao)
{
    const int half_ = threadIdx.x >> 6;
    const int t = blockIdx.x * 2 + half_;
    const int i = threadIdx.x & 63;

    __shared__ float sk[2][DMODEL];
    __shared__ float sv[2][DMODEL];

    const float* kt = k + (size_t)t * DMODEL;
    const float* vt = v + (size_t)t * DMODEL;
#pragma unroll
    for (int f = i; f < 256; f += 64) {
        ((float4*)sk[half_])[f] = ((const float4*)kt)[f];
        ((float4*)sv[half_])[f] = ((const float4*)vt)[f];
    }
    __syncthreads();

    float4 q4[4];
    const float4* qt = (const float4*)(q + (size_t)t * DMODEL + i * NHEAD);
#pragma unroll
    for (int hg = 0; hg < 4; hg++) {
        float4 tq = qt[hg];
        q4[hg] = make_float4(tq.x * 32.0f, tq.y * 32.0f, tq.z * 32.0f, tq.w * 32.0f);
    }

    const float4* k4 = (const float4*)sk[half_];
    const float4* v4 = (const float4*)sv[half_];

    float m = -1e30f, ssum = 0.0f;
    float4 o4[4];
#pragma unroll
    for (int hg = 0; hg < 4; hg++) o4[hg] = make_float4(0.f, 0.f, 0.f, 0.f);

#pragma unroll
    for (int jc = 0; jc < 4; jc++) {
        float sc[16];
        float cm = -1e30f;
#pragma unroll
        for (int jj = 0; jj < 16; jj++) {
            int j = jc * 16 + jj;
            float4 a = make_float4(0.f, 0.f, 0.f, 0.f);
#pragma unroll
            for (int hg = 0; hg < 4; hg++) {
                float4 kk = k4[j * 4 + hg];
                a.x = fmaf(q4[hg].x, kk.x, a.x);
                a.y = fmaf(q4[hg].y, kk.y, a.y);
                a.z = fmaf(q4[hg].z, kk.z, a.z);
                a.w = fmaf(q4[hg].w, kk.w, a.w);
            }
            sc[jj] = (a.x + a.y) + (a.z + a.w);
            cm = fmaxf(cm, sc[jj]);
        }
        float nm = fmaxf(m, cm);
        float scale = __expf(m - nm);
        ssum *= scale;
#pragma unroll
        for (int hg = 0; hg < 4; hg++) {
            o4[hg].x *= scale; o4[hg].y *= scale;
            o4[hg].z *= scale; o4[hg].w *= scale;
        }
#pragma unroll
        for (int jj = 0; jj < 16; jj++) {
            int j = jc * 16 + jj;
            float p = __expf(sc[jj] - nm);
            ssum += p;
#pragma unroll
            for (int hg = 0; hg < 4; hg++) {
                float4 vv = v4[j * 4 + hg];
                o4[hg].x = fmaf(p, vv.x, o4[hg].x);
                o4[hg].y = fmaf(p, vv.y, o4[hg].y);
                o4[hg].z = fmaf(p, vv.z, o4[hg].z);
                o4[hg].w = fmaf(p, vv.w, o4[hg].w);
            }
        }
        m = nm;
    }

    const float inv = 1.0f / ssum;
    uint32_t h8[8];
#pragma unroll
    for (int hg = 0; hg < 4; hg++) {
        __half2 p0 = __floats2half2_rn(o4[hg].x * inv, o4[hg].y * inv);
        __half2 p1 = __floats2half2_rn(o4[hg].z * inv, o4[hg].w * inv);
        h8[hg * 2 + 0] = *reinterpret_cast<uint32_t*>(&p0);
        h8[hg * 2 + 1] = *reinterpret_cast<uint32_t*>(&p1);
    }
    size_t obase = (size_t)t * DMODEL + i * NHEAD;
    *(uint4*)(ao + obase)     = make_uint4(h8[0], h8[1], h8[2], h8[3]);
    *(uint4*)(ao + obase + 8) = make_uint4(h8[4], h8[5], h8[6], h8[7]);
}

// ---------------- launch ----------------
extern "C" void kernel_launch(void* const* d_in, const int* in_sizes, int n_in,
                              void* d_out, int out_size)
{
    const float* query = (const float*)d_in[0];
    const float* key_  = (const float*)d_in[1];
    const float* value = (const float*)d_in[2];
    const float* Wq    = (const float*)d_in[3];
    const float* bq    = (const float*)d_in[4];
    const float* Wk    = (const float*)d_in[5];
    const float* bk    = (const float*)d_in[6];
    const float* Wv    = (const float*)d_in[7];
    const float* bv    = (const float*)d_in[8];
    const float* Wo    = (const float*)d_in[9];
    const float* bo    = (const float*)d_in[10];
    float* out = (float*)d_out;

    float *q, *k, *v;
    __nv_bfloat16 *xh, *xl, *wh, *wl;
    cudaGetSymbolAddress((void**)&q,  g_q);
    cudaGetSymbolAddress((void**)&k,  g_k);
    cudaGetSymbolAddress((void**)&v,  g_v);
    cudaGetSymbolAddress((void**)&xh, g_xh);
    cudaGetSymbolAddress((void**)&xl, g_xl);
    cudaGetSymbolAddress((void**)&wh, g_wh);
    cudaGetSymbolAddress((void**)&wl, g_wl);

    cudaFuncSetAttribute(gemm_bf16x3, cudaFuncAttributeMaxDynamicSharedMemorySize, GSMEM_TOTAL);
    cudaFuncSetAttribute(gemm_fp16x1, cudaFuncAttributeMaxDynamicSharedMemorySize, H1SMEM_TOTAL);

    const int nAct4 = (int)(ACT_ELEMS / 4);
    const int nW4   = (int)(W_ELEMS / 4);
    dim3 sgA((nAct4 + 255) / 256, 3);
    dim3 sgW((nW4 + 255) / 256, 4);
    dim3 ggrid(DMODEL / GBN, MTOK / GBM);   // (8, 128)

    split_acts_kernel<<<sgA, 256>>>((const float4*)query, (const float4*)key_,
                                    (const float4*)value, (uint2*)xh, (uint2*)xl, nAct4);
    split_w_kernel<<<sgW, 256>>>((const float4*)Wq, (const float4*)Wk,
                                 (const float4*)Wv, (const float4*)Wo,
                                 (uint2*)wh, (uint2*)wl, nW4);

    // Q, K projections: bf16x3 (score-critical precision)
    gemm_bf16x3<<<ggrid, 256, GSMEM_TOTAL>>>(xh,             xl,             wh,           wl,           bq, q);
    gemm_bf16x3<<<ggrid, 256, GSMEM_TOTAL>>>(xh + ACT_ELEMS, xl + ACT_ELEMS, wh + W_ELEMS, wl + W_ELEMS, bk, k);
    // V projection: fp16 single product
    gemm_fp16x1<<<ggrid, 256, H1SMEM_TOTAL>>>((const __half*)(xh + 2 * ACT_ELEMS),
                                              (const __half*)(wh + 2 * W_ELEMS), bv, v);

    // attention: writes ao fp16 into slice 0 of xh
    attn_per_token<<<MTOK / 2, 128>>>(q, k, v, (__half*)xh);

    // O projection: fp16 single product
    gemm_fp16x1<<<ggrid, 256, H1SMEM_TOTAL>>>((const __half*)xh,
                                              (const __half*)(wh + 3 * W_ELEMS), bo, out);
}